// round 3
// baseline (speedup 1.0000x reference)
#include <cuda_runtime.h>

// DNAShapeNet fused kernel, R2: packed f32x2 (FFMA2) convolutions.
// 4x (Conv1d + ReLU + BN) + per-position MLP, fully fused in smem.
// B=128, S=8192, channels 4->32->32->32->32, kernels {3,3,5,7}, MLP 32->16->1.

#define BATCH    128
#define SEQ      8192
#define TSIZE    512
#define NTHREADS 512
#define WPAD     544
#define HALO     7

typedef unsigned long long ull;

// ---- smem layout (float offsets) ----
#define OFF_BUFA 0
#define OFF_BUFB (OFF_BUFA + 32*WPAD)
#define OFF_W0   (OFF_BUFB + 32*WPAD)
#define OFF_W1   (OFF_W0 + 384)
#define OFF_W2   (OFF_W1 + 3072)
#define OFF_W3   (OFF_W2 + 5120)
#define OFF_SC   (OFF_W3 + 7168)
#define OFF_SH   (OFF_SC + 128)
#define OFF_BI   (OFF_SH + 128)
#define OFF_FW1  (OFF_BI + 128)
#define OFF_FB1  (OFF_FW1 + 512)
#define OFF_FW2  (OFF_FB1 + 16)
#define OFF_FB2  (OFF_FW2 + 16)
#define SMEM_FLOATS (OFF_FB2 + 1)
#define SMEM_BYTES  (SMEM_FLOATS * 4)

struct Ptrs {
    const float* x;
    const float* w[4];
    const float* b[4];
    const float* g[4];
    const float* bb[4];
    const float* rm[4];
    const float* rv[4];
    const float* fw1;
    const float* fb1;
    const float* fw2;
    const float* fb2;
};

__device__ __forceinline__ ull pack2(float lo, float hi) {
    ull r;
    asm("mov.b64 %0, {%1, %2};" : "=l"(r) : "f"(lo), "f"(hi));
    return r;
}
__device__ __forceinline__ void unpack2(ull v, float& lo, float& hi) {
    asm("mov.b64 {%0, %1}, %2;" : "=f"(lo), "=f"(hi) : "l"(v));
}
__device__ __forceinline__ ull fma2(ull a, ull b, ull c) {
    ull d;
    asm("fma.rn.f32x2 %0, %1, %2, %3;" : "=l"(d) : "l"(a), "l"(b), "l"(c));
    return d;
}

// Process CHP output pairs for one input channel.
// vin: aligned pair pointer; wp: K broadcast weight pairs; acc: CHP pair accs.
// Tap t uses shift s = t + DELTA relative to the aligned base:
//   even s=2m -> v[p+m] ; odd s=2m+1 -> w[p+m] = {v[p+m].hi, v[p+m+1].lo}
template<int K, int DELTA, int CHP, int E>
__device__ __forceinline__ void conv_chunk(const ull* __restrict__ vin,
                                           const ull* __restrict__ wp,
                                           ull* __restrict__ acc)
{
    ull v[CHP + E];
#pragma unroll
    for (int i = 0; i < CHP + E; ++i) v[i] = vin[i];

    ull w[CHP + E - 1];
#pragma unroll
    for (int q = 0; q < CHP + E - 1; ++q) {
        float lo0, hi0, lo1, hi1;
        unpack2(v[q], lo0, hi0);
        unpack2(v[q + 1], lo1, hi1);
        w[q] = pack2(hi0, lo1);
    }

#pragma unroll
    for (int t = 0; t < K; ++t) {
        constexpr int D = DELTA;
        const int s = t + D;
#pragma unroll
        for (int p = 0; p < CHP; ++p) {
            ull op = (s & 1) ? w[p + (s >> 1)] : v[p + (s >> 1)];
            acc[p] = fma2(op, wp[t], acc[p]);
        }
    }
}

// One conv+ReLU+BN layer, smem -> smem, packed-pair math.
// Thread (co, j) computes channel co at 34 positions starting at LOFF + j*34.
template <int CIN, int K, int WOUT, int LOFF, int DELTA>
__device__ __forceinline__ void conv_layer(
    const float* __restrict__ sin, float* __restrict__ sout,
    const float* __restrict__ wgt,
    const float* __restrict__ sc, const float* __restrict__ sh,
    const float* __restrict__ bi,
    int co, int j, int seq_base)
{
    constexpr int H = K / 2;
    constexpr int E = (DELTA + K) / 2;     // extra pairs needed beyond CHP
    constexpr int PAIRS = 17;              // 34 positions per thread

    ull acc[PAIRS];
    const ull z = pack2(0.f, 0.f);
#pragma unroll
    for (int p = 0; p < PAIRS; ++p) acc[p] = z;

    const int abase = (LOFF - H - DELTA) + j * 34;   // even by construction
    const float* wrow = wgt + co * (CIN * K);

#pragma unroll 1
    for (int cin = 0; cin < CIN; ++cin) {
        ull wp[K];
#pragma unroll
        for (int t = 0; t < K; ++t) {
            float wv = wrow[cin * K + t];
            wp[t] = pack2(wv, wv);
        }
        const ull* vin = (const ull*)(sin + cin * WPAD + abase);
        conv_chunk<K, DELTA, 9, E>(vin,     wp, acc);
        conv_chunk<K, DELTA, 8, E>(vin + 9, wp, acc + 9);
    }

    const float scale = sc[co];
    const float shift = sh[co];
    const float bias  = bi[co];
    float* orow = sout + co * WPAD;

#pragma unroll
    for (int p = 0; p < PAIRS; ++p) {
        float lo, hi;
        unpack2(acc[p], lo, hi);
#pragma unroll
        for (int e = 0; e < 2; ++e) {
            float a = e ? hi : lo;
            int pl = j * 34 + 2 * p + e;
            if (pl < WOUT) {
                int u = LOFF + pl;
                int seq = seq_base + u;
                float y = fmaxf(a + bias, 0.f);
                orow[u] = (seq >= 0 && seq < SEQ) ? fmaf(y, scale, shift) : 0.f;
            }
        }
    }
}

__global__ void __launch_bounds__(NTHREADS, 1)
dna_fused_kernel(Ptrs P, float* __restrict__ out)
{
    extern __shared__ float sm[];
    const int tid = threadIdx.x;
    const int ts  = blockIdx.x * TSIZE;
    const int b   = blockIdx.y;
    const int seq_base = ts - HALO;

    float* bufA = sm + OFF_BUFA;
    float* bufB = sm + OFF_BUFB;
    float* sW[4] = { sm + OFF_W0, sm + OFF_W1, sm + OFF_W2, sm + OFF_W3 };
    float* sSC = sm + OFF_SC;
    float* sSH = sm + OFF_SH;
    float* sBI = sm + OFF_BI;
    float* sFW1 = sm + OFF_FW1;
    float* sFB1 = sm + OFF_FB1;
    float* sFW2 = sm + OFF_FW2;
    float* sFB2 = sm + OFF_FB2;

    const int wn[4] = { 32 * 4 * 3, 32 * 32 * 3, 32 * 32 * 5, 32 * 32 * 7 };
#pragma unroll
    for (int l = 0; l < 4; ++l)
        for (int i = tid; i < wn[l]; i += NTHREADS) sW[l][i] = P.w[l][i];

    for (int i = tid; i < 16 * 32; i += NTHREADS) sFW1[i] = P.fw1[i];
    if (tid < 16) { sFB1[tid] = P.fb1[tid]; sFW2[tid] = P.fw2[tid]; }
    if (tid == 0) sFB2[0] = P.fb2[0];

    if (tid < 128) {
        int l = tid >> 5, c = tid & 31;
        float inv = P.g[l][c] * rsqrtf(P.rv[l][c] + 1e-5f);
        sSC[tid] = inv;
        sSH[tid] = P.bb[l][c] - P.rm[l][c] * inv;
        sBI[tid] = P.b[l][c];
    }

    constexpr int WIN = TSIZE + 2 * HALO;   // 526
    for (int idx = tid; idx < 4 * WIN; idx += NTHREADS) {
        int cin = idx / WIN;
        int u = idx - cin * WIN;
        int seq = seq_base + u;
        bufA[cin * WPAD + u] =
            (seq >= 0 && seq < SEQ) ? P.x[(b * 4 + cin) * SEQ + seq] : 0.f;
    }
    __syncthreads();

    const int co = tid >> 4;
    const int j  = tid & 15;

    // aligned bases (LOFF-H-DELTA): L0:0  L1:0(delta=1)  L2:2  L3:4  — all even
    conv_layer<4, 3, 524, 1, 0>(bufA, bufB, sW[0], sSC +  0, sSH +  0, sBI +  0, co, j, seq_base);
    __syncthreads();
    conv_layer<32, 3, 522, 2, 1>(bufB, bufA, sW[1], sSC + 32, sSH + 32, sBI + 32, co, j, seq_base);
    __syncthreads();
    conv_layer<32, 5, 518, 4, 0>(bufA, bufB, sW[2], sSC + 64, sSH + 64, sBI + 64, co, j, seq_base);
    __syncthreads();
    conv_layer<32, 7, 512, 7, 0>(bufB, bufA, sW[3], sSC + 96, sSH + 96, sBI + 96, co, j, seq_base);
    __syncthreads();

    // ---- per-position MLP: 32 -> 16 (ReLU) -> 1, packed pairs ----
    float yc[32];
#pragma unroll
    for (int c = 0; c < 32; ++c) yc[c] = bufA[c * WPAD + HALO + tid];

    ull yp[16];
#pragma unroll
    for (int i = 0; i < 16; ++i) yp[i] = pack2(yc[2 * i], yc[2 * i + 1]);

    float o = sFB2[0];
#pragma unroll
    for (int i = 0; i < 16; ++i) {
        ull hp = pack2(sFB1[i], 0.f);
        const ull* fwp = (const ull*)(sFW1 + i * 32);
#pragma unroll
        for (int c = 0; c < 16; ++c) hp = fma2(fwp[c], yp[c], hp);
        float hlo, hhi;
        unpack2(hp, hlo, hhi);
        float h = hlo + hhi;
        o = fmaf(fmaxf(h, 0.f), sFW2[i], o);
    }
    out[b * SEQ + ts + tid] = o;
}

extern "C" void kernel_launch(void* const* d_in, const int* in_sizes, int n_in,
                              void* d_out, int out_size)
{
    Ptrs P;
    P.x = (const float*)d_in[0];
    for (int l = 0; l < 4; ++l) {
        P.w[l]  = (const float*)d_in[1 + 6 * l];
        P.b[l]  = (const float*)d_in[2 + 6 * l];
        P.g[l]  = (const float*)d_in[3 + 6 * l];
        P.bb[l] = (const float*)d_in[4 + 6 * l];
        P.rm[l] = (const float*)d_in[5 + 6 * l];
        P.rv[l] = (const float*)d_in[6 + 6 * l];
    }
    P.fw1 = (const float*)d_in[25];
    P.fb1 = (const float*)d_in[26];
    P.fw2 = (const float*)d_in[27];
    P.fb2 = (const float*)d_in[28];

    cudaFuncSetAttribute(dna_fused_kernel,
                         cudaFuncAttributeMaxDynamicSharedMemorySize, SMEM_BYTES);

    dim3 grid(SEQ / TSIZE, BATCH);
    dna_fused_kernel<<<grid, NTHREADS, SMEM_BYTES>>>(P, (float*)d_out);
}

// round 4
// speedup vs baseline: 1.2815x; 1.2815x over previous
#include <cuda_runtime.h>

// DNAShapeNet fused kernel, R3: channel-pair packed f32x2 convolutions.
// Pair = (co, co+1) at same position -> no tap-shift repacking; input is
// broadcast-packed once per scalar (amortized over K taps); weight pairs
// pre-interleaved in smem. 4x (Conv1d+ReLU+BN) + MLP, fully fused.

#define BATCH    128
#define SEQ      8192
#define TSIZE    512
#define NTHREADS 512
#define WPAD     592
#define HALO     7

typedef unsigned long long ull;

// ---- smem layout (float offsets) ----
#define OFF_BUFA 0
#define OFF_BUFB (OFF_BUFA + 32*WPAD)     // 18944
#define OFF_W0   (OFF_BUFB + 32*WPAD)     // 37888 ; interleaved pairs 32*4*3
#define OFF_W1   (OFF_W0 + 384)
#define OFF_W2   (OFF_W1 + 3072)
#define OFF_W3   (OFF_W2 + 5120)
#define OFF_SC   (OFF_W3 + 7168)
#define OFF_SH   (OFF_SC + 128)
#define OFF_BI   (OFF_SH + 128)
#define OFF_FW1  (OFF_BI + 128)
#define OFF_FB1  (OFF_FW1 + 512)
#define OFF_FW2  (OFF_FB1 + 16)
#define OFF_FB2  (OFF_FW2 + 16)
#define SMEM_FLOATS (OFF_FB2 + 1)
#define SMEM_BYTES  (SMEM_FLOATS * 4)     // ~218 KB

struct Ptrs {
    const float* x;
    const float* w[4];
    const float* b[4];
    const float* g[4];
    const float* bb[4];
    const float* rm[4];
    const float* rv[4];
    const float* fw1;
    const float* fb1;
    const float* fw2;
    const float* fb2;
};

__device__ __forceinline__ ull pack2(float lo, float hi) {
    ull r;
    asm("mov.b64 %0, {%1, %2};" : "=l"(r) : "f"(lo), "f"(hi));
    return r;
}
__device__ __forceinline__ void unpack2(ull v, float& lo, float& hi) {
    asm("mov.b64 {%0, %1}, %2;" : "=f"(lo), "=f"(hi) : "l"(v));
}
__device__ __forceinline__ ull fma2(ull a, ull b, ull c) {
    ull d;
    asm("fma.rn.f32x2 %0, %1, %2, %3;" : "=l"(d) : "l"(a), "l"(b), "l"(c));
    return d;
}

// CH output positions for one input channel, channel-pair packed.
// xin: even-aligned scalar smem pointer. SOFF: parity offset of the first
// needed scalar within the even window. wp: K channel-pair weights.
template<int K, int CH, int SOFF>
__device__ __forceinline__ void conv_chunk_cp(const float* __restrict__ xin,
                                              const ull* __restrict__ wp,
                                              ull* __restrict__ acc)
{
    constexpr int NS = SOFF + CH + K - 1;   // scalars spanned from even base
    constexpr int NP = (NS + 1) >> 1;       // float2 loads

    float s[2 * NP];
#pragma unroll
    for (int i = 0; i < NP; ++i) {
        float2 v = ((const float2*)xin)[i];
        s[2 * i] = v.x; s[2 * i + 1] = v.y;
    }

    ull bb[NS];                             // broadcast pairs {s,s}
#pragma unroll
    for (int u = SOFF; u < NS; ++u) bb[u] = pack2(s[u], s[u]);

#pragma unroll
    for (int t = 0; t < K; ++t)
#pragma unroll
        for (int p = 0; p < CH; ++p)
            acc[p] = fma2(bb[SOFF + p + t], wp[t], acc[p]);
}

// One conv+ReLU+BN layer, smem -> smem. Thread (cp, j) computes channels
// {2cp, 2cp+1} at 18 positions starting at LOFF + j*18.
template <int CIN, int K, int WOUT, int LOFF>
__device__ __forceinline__ void conv_layer_cp(
    const float* __restrict__ sin, float* __restrict__ sout,
    const float* __restrict__ wint,
    const float* __restrict__ sc, const float* __restrict__ sh,
    const float* __restrict__ bi,
    int cp, int j, int seq_base)
{
    constexpr int H = K / 2;
    constexpr int DELTA = (LOFF - H) & 1;        // parity fix -> even base
    constexpr int S1    = (9 + DELTA) & 1;       // chunk-1 parity
    constexpr int POFF1 = (9 + DELTA) >> 1;      // chunk-1 pair offset

    ull acc[18];
    const ull z = pack2(0.f, 0.f);
#pragma unroll
    for (int p = 0; p < 18; ++p) acc[p] = z;

    const int abase = (LOFF - H - DELTA) + j * 18;   // even

#pragma unroll 1
    for (int cin = 0; cin < CIN; ++cin) {
        const ull* wsm = (const ull*)(wint + (cp * CIN + cin) * (2 * K));
        ull wp[K];
#pragma unroll
        for (int t = 0; t < K; ++t) wp[t] = wsm[t];   // LDS.64, warp-uniform

        const float* xin = sin + cin * WPAD + abase;
        conv_chunk_cp<K, 9, DELTA>(xin, wp, acc);
        conv_chunk_cp<K, 9, S1>(xin + 2 * POFF1, wp, acc + 9);
    }

    const int co0 = 2 * cp;
    const float sc0 = sc[co0], sh0 = sh[co0], bi0 = bi[co0];
    const float sc1 = sc[co0 + 1], sh1 = sh[co0 + 1], bi1 = bi[co0 + 1];
    float* o0 = sout + co0 * WPAD;
    float* o1 = o0 + WPAD;

#pragma unroll
    for (int i = 0; i < 18; ++i) {
        int pl = j * 18 + i;
        if (pl < WOUT) {
            int u = LOFF + pl;
            int seq = seq_base + u;
            bool inb = (seq >= 0 && seq < SEQ);
            float a0, a1;
            unpack2(acc[i], a0, a1);
            float y0 = fmaxf(a0 + bi0, 0.f);
            float y1 = fmaxf(a1 + bi1, 0.f);
            o0[u] = inb ? fmaf(y0, sc0, sh0) : 0.f;
            o1[u] = inb ? fmaf(y1, sc1, sh1) : 0.f;
        }
    }
}

__global__ void __launch_bounds__(NTHREADS, 1)
dna_fused_kernel(Ptrs P, float* __restrict__ out)
{
    extern __shared__ float sm[];
    const int tid = threadIdx.x;
    const int ts  = blockIdx.x * TSIZE;
    const int b   = blockIdx.y;
    const int seq_base = ts - HALO;

    float* bufA = sm + OFF_BUFA;
    float* bufB = sm + OFF_BUFB;
    float* sW[4] = { sm + OFF_W0, sm + OFF_W1, sm + OFF_W2, sm + OFF_W3 };
    float* sSC = sm + OFF_SC;
    float* sSH = sm + OFF_SH;
    float* sBI = sm + OFF_BI;
    float* sFW1 = sm + OFF_FW1;
    float* sFB1 = sm + OFF_FB1;
    float* sFW2 = sm + OFF_FW2;
    float* sFB2 = sm + OFF_FB2;

    // phase 1: zero activation buffers; load (interleaved) weights + params
    for (int i = tid; i < 2 * 32 * WPAD; i += NTHREADS) sm[i] = 0.f;

    const int cinK[4] = { 4 * 3, 32 * 3, 32 * 5, 32 * 7 };
#pragma unroll
    for (int l = 0; l < 4; ++l) {
        const int n = cinK[l];                 // per-channel weight count
        for (int i = tid; i < 16 * n; i += NTHREADS) {
            int cp = i / n, r = i - cp * n;
            sW[l][2 * i]     = P.w[l][(2 * cp)     * n + r];
            sW[l][2 * i + 1] = P.w[l][(2 * cp + 1) * n + r];
        }
    }

    for (int i = tid; i < 16 * 32; i += NTHREADS) sFW1[i] = P.fw1[i];
    if (tid < 16) { sFB1[tid] = P.fb1[tid]; sFW2[tid] = P.fw2[tid]; }
    if (tid == 0) sFB2[0] = P.fb2[0];

    if (tid < 128) {
        int l = tid >> 5, c = tid & 31;
        float inv = P.g[l][c] * rsqrtf(P.rv[l][c] + 1e-5f);
        sSC[tid] = inv;
        sSH[tid] = P.bb[l][c] - P.rm[l][c] * inv;
        sBI[tid] = P.b[l][c];
    }
    __syncthreads();

    // phase 2: input tile (4 channels, width 526) into zeroed bufA
    constexpr int WIN = TSIZE + 2 * HALO;   // 526
    for (int idx = tid; idx < 4 * WIN; idx += NTHREADS) {
        int cin = idx / WIN;
        int u = idx - cin * WIN;
        int seq = seq_base + u;
        if (seq >= 0 && seq < SEQ)
            bufA[cin * WPAD + u] = P.x[(b * 4 + cin) * SEQ + seq];
    }
    __syncthreads();

    const int cp = tid >> 5;    // warp -> channel pair
    const int j  = tid & 31;    // lane -> 18-position slice

    conv_layer_cp<4, 3, 524, 1>(bufA, bufB, sW[0], sSC +  0, sSH +  0, sBI +  0, cp, j, seq_base);
    __syncthreads();
    conv_layer_cp<32, 3, 522, 2>(bufB, bufA, sW[1], sSC + 32, sSH + 32, sBI + 32, cp, j, seq_base);
    __syncthreads();
    conv_layer_cp<32, 5, 518, 4>(bufA, bufB, sW[2], sSC + 64, sSH + 64, sBI + 64, cp, j, seq_base);
    __syncthreads();
    conv_layer_cp<32, 7, 512, 7>(bufB, bufA, sW[3], sSC + 96, sSH + 96, sBI + 96, cp, j, seq_base);
    __syncthreads();

    // ---- per-position MLP: 32 -> 16 (ReLU) -> 1 ; one thread per position ----
    float yc[32];
#pragma unroll
    for (int c = 0; c < 32; ++c) yc[c] = bufA[c * WPAD + HALO + tid];

    float o = sFB2[0];
#pragma unroll
    for (int i = 0; i < 16; ++i) {
        float h = sFB1[i];
#pragma unroll
        for (int c = 0; c < 32; ++c) h = fmaf(sFW1[i * 32 + c], yc[c], h);
        o = fmaf(fmaxf(h, 0.f), sFW2[i], o);
    }
    out[b * SEQ + ts + tid] = o;
}

extern "C" void kernel_launch(void* const* d_in, const int* in_sizes, int n_in,
                              void* d_out, int out_size)
{
    Ptrs P;
    P.x = (const float*)d_in[0];
    for (int l = 0; l < 4; ++l) {
        P.w[l]  = (const float*)d_in[1 + 6 * l];
        P.b[l]  = (const float*)d_in[2 + 6 * l];
        P.g[l]  = (const float*)d_in[3 + 6 * l];
        P.bb[l] = (const float*)d_in[4 + 6 * l];
        P.rm[l] = (const float*)d_in[5 + 6 * l];
        P.rv[l] = (const float*)d_in[6 + 6 * l];
    }
    P.fw1 = (const float*)d_in[25];
    P.fb1 = (const float*)d_in[26];
    P.fw2 = (const float*)d_in[27];
    P.fb2 = (const float*)d_in[28];

    cudaFuncSetAttribute(dna_fused_kernel,
                         cudaFuncAttributeMaxDynamicSharedMemorySize, SMEM_BYTES);

    dim3 grid(SEQ / TSIZE, BATCH);
    dna_fused_kernel<<<grid, NTHREADS, SMEM_BYTES>>>(P, (float*)d_out);
}

// round 5
// speedup vs baseline: 1.2820x; 1.0004x over previous
#include <cuda_runtime.h>

// DNAShapeNet fused kernel, R3: channel-pair packed f32x2 convolutions.
// Pair = (co, co+1) at same position -> no tap-shift repacking; input is
// broadcast-packed once per scalar (amortized over K taps); weight pairs
// pre-interleaved in smem. 4x (Conv1d+ReLU+BN) + MLP, fully fused.

#define BATCH    128
#define SEQ      8192
#define TSIZE    512
#define NTHREADS 512
#define WPAD     592
#define HALO     7

typedef unsigned long long ull;

// ---- smem layout (float offsets) ----
#define OFF_BUFA 0
#define OFF_BUFB (OFF_BUFA + 32*WPAD)     // 18944
#define OFF_W0   (OFF_BUFB + 32*WPAD)     // 37888 ; interleaved pairs 32*4*3
#define OFF_W1   (OFF_W0 + 384)
#define OFF_W2   (OFF_W1 + 3072)
#define OFF_W3   (OFF_W2 + 5120)
#define OFF_SC   (OFF_W3 + 7168)
#define OFF_SH   (OFF_SC + 128)
#define OFF_BI   (OFF_SH + 128)
#define OFF_FW1  (OFF_BI + 128)
#define OFF_FB1  (OFF_FW1 + 512)
#define OFF_FW2  (OFF_FB1 + 16)
#define OFF_FB2  (OFF_FW2 + 16)
#define SMEM_FLOATS (OFF_FB2 + 1)
#define SMEM_BYTES  (SMEM_FLOATS * 4)     // ~218 KB

struct Ptrs {
    const float* x;
    const float* w[4];
    const float* b[4];
    const float* g[4];
    const float* bb[4];
    const float* rm[4];
    const float* rv[4];
    const float* fw1;
    const float* fb1;
    const float* fw2;
    const float* fb2;
};

__device__ __forceinline__ ull pack2(float lo, float hi) {
    ull r;
    asm("mov.b64 %0, {%1, %2};" : "=l"(r) : "f"(lo), "f"(hi));
    return r;
}
__device__ __forceinline__ void unpack2(ull v, float& lo, float& hi) {
    asm("mov.b64 {%0, %1}, %2;" : "=f"(lo), "=f"(hi) : "l"(v));
}
__device__ __forceinline__ ull fma2(ull a, ull b, ull c) {
    ull d;
    asm("fma.rn.f32x2 %0, %1, %2, %3;" : "=l"(d) : "l"(a), "l"(b), "l"(c));
    return d;
}

// CH output positions for one input channel, channel-pair packed.
// xin: even-aligned scalar smem pointer. SOFF: parity offset of the first
// needed scalar within the even window. wp: K channel-pair weights.
template<int K, int CH, int SOFF>
__device__ __forceinline__ void conv_chunk_cp(const float* __restrict__ xin,
                                              const ull* __restrict__ wp,
                                              ull* __restrict__ acc)
{
    constexpr int NS = SOFF + CH + K - 1;   // scalars spanned from even base
    constexpr int NP = (NS + 1) >> 1;       // float2 loads

    float s[2 * NP];
#pragma unroll
    for (int i = 0; i < NP; ++i) {
        float2 v = ((const float2*)xin)[i];
        s[2 * i] = v.x; s[2 * i + 1] = v.y;
    }

    ull bb[NS];                             // broadcast pairs {s,s}
#pragma unroll
    for (int u = SOFF; u < NS; ++u) bb[u] = pack2(s[u], s[u]);

#pragma unroll
    for (int t = 0; t < K; ++t)
#pragma unroll
        for (int p = 0; p < CH; ++p)
            acc[p] = fma2(bb[SOFF + p + t], wp[t], acc[p]);
}

// One conv+ReLU+BN layer, smem -> smem. Thread (cp, j) computes channels
// {2cp, 2cp+1} at 18 positions starting at LOFF + j*18.
template <int CIN, int K, int WOUT, int LOFF>
__device__ __forceinline__ void conv_layer_cp(
    const float* __restrict__ sin, float* __restrict__ sout,
    const float* __restrict__ wint,
    const float* __restrict__ sc, const float* __restrict__ sh,
    const float* __restrict__ bi,
    int cp, int j, int seq_base)
{
    constexpr int H = K / 2;
    constexpr int DELTA = (LOFF - H) & 1;        // parity fix -> even base
    constexpr int S1    = (9 + DELTA) & 1;       // chunk-1 parity
    constexpr int POFF1 = (9 + DELTA) >> 1;      // chunk-1 pair offset

    ull acc[18];
    const ull z = pack2(0.f, 0.f);
#pragma unroll
    for (int p = 0; p < 18; ++p) acc[p] = z;

    const int abase = (LOFF - H - DELTA) + j * 18;   // even

#pragma unroll 1
    for (int cin = 0; cin < CIN; ++cin) {
        const ull* wsm = (const ull*)(wint + (cp * CIN + cin) * (2 * K));
        ull wp[K];
#pragma unroll
        for (int t = 0; t < K; ++t) wp[t] = wsm[t];   // LDS.64, warp-uniform

        const float* xin = sin + cin * WPAD + abase;
        conv_chunk_cp<K, 9, DELTA>(xin, wp, acc);
        conv_chunk_cp<K, 9, S1>(xin + 2 * POFF1, wp, acc + 9);
    }

    const int co0 = 2 * cp;
    const float sc0 = sc[co0], sh0 = sh[co0], bi0 = bi[co0];
    const float sc1 = sc[co0 + 1], sh1 = sh[co0 + 1], bi1 = bi[co0 + 1];
    float* o0 = sout + co0 * WPAD;
    float* o1 = o0 + WPAD;

#pragma unroll
    for (int i = 0; i < 18; ++i) {
        int pl = j * 18 + i;
        if (pl < WOUT) {
            int u = LOFF + pl;
            int seq = seq_base + u;
            bool inb = (seq >= 0 && seq < SEQ);
            float a0, a1;
            unpack2(acc[i], a0, a1);
            float y0 = fmaxf(a0 + bi0, 0.f);
            float y1 = fmaxf(a1 + bi1, 0.f);
            o0[u] = inb ? fmaf(y0, sc0, sh0) : 0.f;
            o1[u] = inb ? fmaf(y1, sc1, sh1) : 0.f;
        }
    }
}

__global__ void __launch_bounds__(NTHREADS, 1)
dna_fused_kernel(Ptrs P, float* __restrict__ out)
{
    extern __shared__ float sm[];
    const int tid = threadIdx.x;
    const int ts  = blockIdx.x * TSIZE;
    const int b   = blockIdx.y;
    const int seq_base = ts - HALO;

    float* bufA = sm + OFF_BUFA;
    float* bufB = sm + OFF_BUFB;
    float* sW[4] = { sm + OFF_W0, sm + OFF_W1, sm + OFF_W2, sm + OFF_W3 };
    float* sSC = sm + OFF_SC;
    float* sSH = sm + OFF_SH;
    float* sBI = sm + OFF_BI;
    float* sFW1 = sm + OFF_FW1;
    float* sFB1 = sm + OFF_FB1;
    float* sFW2 = sm + OFF_FW2;
    float* sFB2 = sm + OFF_FB2;

    // phase 1: zero activation buffers; load (interleaved) weights + params
    for (int i = tid; i < 2 * 32 * WPAD; i += NTHREADS) sm[i] = 0.f;

    const int cinK[4] = { 4 * 3, 32 * 3, 32 * 5, 32 * 7 };
#pragma unroll
    for (int l = 0; l < 4; ++l) {
        const int n = cinK[l];                 // per-channel weight count
        for (int i = tid; i < 16 * n; i += NTHREADS) {
            int cp = i / n, r = i - cp * n;
            sW[l][2 * i]     = P.w[l][(2 * cp)     * n + r];
            sW[l][2 * i + 1] = P.w[l][(2 * cp + 1) * n + r];
        }
    }

    for (int i = tid; i < 16 * 32; i += NTHREADS) sFW1[i] = P.fw1[i];
    if (tid < 16) { sFB1[tid] = P.fb1[tid]; sFW2[tid] = P.fw2[tid]; }
    if (tid == 0) sFB2[0] = P.fb2[0];

    if (tid < 128) {
        int l = tid >> 5, c = tid & 31;
        float inv = P.g[l][c] * rsqrtf(P.rv[l][c] + 1e-5f);
        sSC[tid] = inv;
        sSH[tid] = P.bb[l][c] - P.rm[l][c] * inv;
        sBI[tid] = P.b[l][c];
    }
    __syncthreads();

    // phase 2: input tile (4 channels, width 526) into zeroed bufA
    constexpr int WIN = TSIZE + 2 * HALO;   // 526
    for (int idx = tid; idx < 4 * WIN; idx += NTHREADS) {
        int cin = idx / WIN;
        int u = idx - cin * WIN;
        int seq = seq_base + u;
        if (seq >= 0 && seq < SEQ)
            bufA[cin * WPAD + u] = P.x[(b * 4 + cin) * SEQ + seq];
    }
    __syncthreads();

    const int cp = tid >> 5;    // warp -> channel pair
    const int j  = tid & 31;    // lane -> 18-position slice

    conv_layer_cp<4, 3, 524, 1>(bufA, bufB, sW[0], sSC +  0, sSH +  0, sBI +  0, cp, j, seq_base);
    __syncthreads();
    conv_layer_cp<32, 3, 522, 2>(bufB, bufA, sW[1], sSC + 32, sSH + 32, sBI + 32, cp, j, seq_base);
    __syncthreads();
    conv_layer_cp<32, 5, 518, 4>(bufA, bufB, sW[2], sSC + 64, sSH + 64, sBI + 64, cp, j, seq_base);
    __syncthreads();
    conv_layer_cp<32, 7, 512, 7>(bufB, bufA, sW[3], sSC + 96, sSH + 96, sBI + 96, cp, j, seq_base);
    __syncthreads();

    // ---- per-position MLP: 32 -> 16 (ReLU) -> 1 ; one thread per position ----
    float yc[32];
#pragma unroll
    for (int c = 0; c < 32; ++c) yc[c] = bufA[c * WPAD + HALO + tid];

    float o = sFB2[0];
#pragma unroll
    for (int i = 0; i < 16; ++i) {
        float h = sFB1[i];
#pragma unroll
        for (int c = 0; c < 32; ++c) h = fmaf(sFW1[i * 32 + c], yc[c], h);
        o = fmaf(fmaxf(h, 0.f), sFW2[i], o);
    }
    out[b * SEQ + ts + tid] = o;
}

extern "C" void kernel_launch(void* const* d_in, const int* in_sizes, int n_in,
                              void* d_out, int out_size)
{
    Ptrs P;
    P.x = (const float*)d_in[0];
    for (int l = 0; l < 4; ++l) {
        P.w[l]  = (const float*)d_in[1 + 6 * l];
        P.b[l]  = (const float*)d_in[2 + 6 * l];
        P.g[l]  = (const float*)d_in[3 + 6 * l];
        P.bb[l] = (const float*)d_in[4 + 6 * l];
        P.rm[l] = (const float*)d_in[5 + 6 * l];
        P.rv[l] = (const float*)d_in[6 + 6 * l];
    }
    P.fw1 = (const float*)d_in[25];
    P.fb1 = (const float*)d_in[26];
    P.fw2 = (const float*)d_in[27];
    P.fb2 = (const float*)d_in[28];

    cudaFuncSetAttribute(dna_fused_kernel,
                         cudaFuncAttributeMaxDynamicSharedMemorySize, SMEM_BYTES);

    dim3 grid(SEQ / TSIZE, BATCH);
    dna_fused_kernel<<<grid, NTHREADS, SMEM_BYTES>>>(P, (float*)d_out);
}

// round 6
// speedup vs baseline: 1.4243x; 1.1110x over previous
#include <cuda_runtime.h>

// DNAShapeNet fused kernel, R4: channel-pair f32x2 convs, single 18-pos chunk,
// halo-only zero fill. 4x (Conv1d+ReLU+BN) + MLP, fully fused in smem.

#define BATCH    128
#define SEQ      8192
#define TSIZE    512
#define NTHREADS 512
#define WPAD     592
#define HALO     7

typedef unsigned long long ull;

// ---- smem layout (float offsets) ----
#define OFF_BUFA 0
#define OFF_BUFB (OFF_BUFA + 32*WPAD)
#define OFF_W0   (OFF_BUFB + 32*WPAD)
#define OFF_W1   (OFF_W0 + 384)
#define OFF_W2   (OFF_W1 + 3072)
#define OFF_W3   (OFF_W2 + 5120)
#define OFF_SC   (OFF_W3 + 7168)
#define OFF_SH   (OFF_SC + 128)
#define OFF_BI   (OFF_SH + 128)
#define OFF_FW1  (OFF_BI + 128)
#define OFF_FB1  (OFF_FW1 + 512)
#define OFF_FW2  (OFF_FB1 + 16)
#define OFF_FB2  (OFF_FW2 + 16)
#define SMEM_FLOATS (OFF_FB2 + 1)
#define SMEM_BYTES  (SMEM_FLOATS * 4)

struct Ptrs {
    const float* x;
    const float* w[4];
    const float* b[4];
    const float* g[4];
    const float* bb[4];
    const float* rm[4];
    const float* rv[4];
    const float* fw1;
    const float* fb1;
    const float* fw2;
    const float* fb2;
};

__device__ __forceinline__ ull pack2(float lo, float hi) {
    ull r;
    asm("mov.b64 %0, {%1, %2};" : "=l"(r) : "f"(lo), "f"(hi));
    return r;
}
__device__ __forceinline__ void unpack2(ull v, float& lo, float& hi) {
    asm("mov.b64 {%0, %1}, %2;" : "=f"(lo), "=f"(hi) : "l"(v));
}
__device__ __forceinline__ ull fma2(ull a, ull b, ull c) {
    ull d;
    asm("fma.rn.f32x2 %0, %1, %2, %3;" : "=l"(d) : "l"(a), "l"(b), "l"(c));
    return d;
}

// CH output positions for one input channel, channel-pair packed.
// Single chunk: load all scalars once, broadcast-pack once, K*CH FMA2.
template<int K, int SOFF, int CH>
__device__ __forceinline__ void conv_chunk_cp(const float* __restrict__ xin,
                                              const ull* __restrict__ wp,
                                              ull* __restrict__ acc)
{
    constexpr int NS = SOFF + CH + K - 1;   // scalars spanned from even base
    constexpr int NP = (NS + 1) >> 1;       // float2 loads

    float s[2 * NP];
#pragma unroll
    for (int i = 0; i < NP; ++i) {
        float2 v = ((const float2*)xin)[i];
        s[2 * i] = v.x; s[2 * i + 1] = v.y;
    }

    ull bb[NS];                             // broadcast pairs {s,s}
#pragma unroll
    for (int u = SOFF; u < NS; ++u) bb[u] = pack2(s[u], s[u]);

#pragma unroll
    for (int t = 0; t < K; ++t)
#pragma unroll
        for (int p = 0; p < CH; ++p)
            acc[p] = fma2(bb[SOFF + p + t], wp[t], acc[p]);
}

// One conv+ReLU+BN layer, smem -> smem. Thread (cp, j) computes channels
// {2cp, 2cp+1} at 18 positions starting at LOFF + j*18.
template <int CIN, int K, int WOUT, int LOFF, int UNROLL>
__device__ __forceinline__ void conv_layer_cp(
    const float* __restrict__ sin, float* __restrict__ sout,
    const float* __restrict__ wint,
    const float* __restrict__ sc, const float* __restrict__ sh,
    const float* __restrict__ bi,
    int cp, int j, int seq_base)
{
    constexpr int H = K / 2;
    constexpr int DELTA = (LOFF - H) & 1;        // parity fix -> even base

    ull acc[18];
    const ull z = pack2(0.f, 0.f);
#pragma unroll
    for (int p = 0; p < 18; ++p) acc[p] = z;

    const int abase = (LOFF - H - DELTA) + j * 18;   // even

#pragma unroll UNROLL
    for (int cin = 0; cin < CIN; ++cin) {
        const ull* wsm = (const ull*)(wint + (cp * CIN + cin) * (2 * K));
        ull wp[K];
#pragma unroll
        for (int t = 0; t < K; ++t) wp[t] = wsm[t];   // LDS.64, warp-uniform

        const float* xin = sin + cin * WPAD + abase;
        conv_chunk_cp<K, DELTA, 18>(xin, wp, acc);
    }

    const int co0 = 2 * cp;
    const float sc0 = sc[co0], sh0 = sh[co0], bi0 = bi[co0];
    const float sc1 = sc[co0 + 1], sh1 = sh[co0 + 1], bi1 = bi[co0 + 1];
    float* o0 = sout + co0 * WPAD;
    float* o1 = o0 + WPAD;

#pragma unroll
    for (int i = 0; i < 18; ++i) {
        int pl = j * 18 + i;
        if (pl < WOUT) {
            int u = LOFF + pl;
            int seq = seq_base + u;
            bool inb = (seq >= 0 && seq < SEQ);
            float a0, a1;
            unpack2(acc[i], a0, a1);
            float y0 = fmaxf(a0 + bi0, 0.f);
            float y1 = fmaxf(a1 + bi1, 0.f);
            o0[u] = inb ? fmaf(y0, sc0, sh0) : 0.f;
            o1[u] = inb ? fmaf(y1, sc1, sh1) : 0.f;
        }
    }
}

__global__ void __launch_bounds__(NTHREADS, 1)
dna_fused_kernel(Ptrs P, float* __restrict__ out)
{
    extern __shared__ float sm[];
    const int tid = threadIdx.x;
    const int ts  = blockIdx.x * TSIZE;
    const int b   = blockIdx.y;
    const int seq_base = ts - HALO;

    float* bufA = sm + OFF_BUFA;
    float* bufB = sm + OFF_BUFB;
    float* sW[4] = { sm + OFF_W0, sm + OFF_W1, sm + OFF_W2, sm + OFF_W3 };
    float* sSC = sm + OFF_SC;
    float* sSH = sm + OFF_SH;
    float* sBI = sm + OFF_BI;
    float* sFW1 = sm + OFF_FW1;
    float* sFB1 = sm + OFF_FB1;
    float* sFW2 = sm + OFF_FW2;
    float* sFB2 = sm + OFF_FB2;

    // phase 1: halo-only zero fill of both activation buffers.
    // Per row: [0,8) and [512,592) — covers every layer's over-read/stale range
    // (used conv reads always fall inside the predecessor's written interval).
    {
        constexpr int ZPR = 8 + (WPAD - 512);   // 88 zeros per row
        for (int idx = tid; idx < 64 * ZPR; idx += NTHREADS) {
            int r = idx / ZPR, c = idx - r * ZPR;
            int u = (c < 8) ? c : (504 + c);
            sm[r * WPAD + u] = 0.f;
        }
    }

    const int cinK[4] = { 4 * 3, 32 * 3, 32 * 5, 32 * 7 };
#pragma unroll
    for (int l = 0; l < 4; ++l) {
        const int n = cinK[l];                 // per-channel weight count
        for (int i = tid; i < 16 * n; i += NTHREADS) {
            int cp = i / n, r = i - cp * n;
            sW[l][2 * i]     = P.w[l][(2 * cp)     * n + r];
            sW[l][2 * i + 1] = P.w[l][(2 * cp + 1) * n + r];
        }
    }

    for (int i = tid; i < 16 * 32; i += NTHREADS) sFW1[i] = P.fw1[i];
    if (tid < 16) { sFB1[tid] = P.fb1[tid]; sFW2[tid] = P.fw2[tid]; }
    if (tid == 0) sFB2[0] = P.fb2[0];

    if (tid < 128) {
        int l = tid >> 5, c = tid & 31;
        float inv = P.g[l][c] * rsqrtf(P.rv[l][c] + 1e-5f);
        sSC[tid] = inv;
        sSH[tid] = P.bb[l][c] - P.rm[l][c] * inv;
        sBI[tid] = P.b[l][c];
    }
    __syncthreads();

    // phase 2: input tile (4 channels, width 526) over the zeroed halo
    constexpr int WIN = TSIZE + 2 * HALO;   // 526
    for (int idx = tid; idx < 4 * WIN; idx += NTHREADS) {
        int cin = idx / WIN;
        int u = idx - cin * WIN;
        int seq = seq_base + u;
        if (seq >= 0 && seq < SEQ)
            bufA[cin * WPAD + u] = P.x[(b * 4 + cin) * SEQ + seq];
    }
    __syncthreads();

    const int cp = tid >> 5;    // warp -> channel pair
    const int j  = tid & 31;    // lane -> 18-position slice

    conv_layer_cp<4, 3, 524, 1, 4>(bufA, bufB, sW[0], sSC +  0, sSH +  0, sBI +  0, cp, j, seq_base);
    __syncthreads();
    conv_layer_cp<32, 3, 522, 2, 1>(bufB, bufA, sW[1], sSC + 32, sSH + 32, sBI + 32, cp, j, seq_base);
    __syncthreads();
    conv_layer_cp<32, 5, 518, 4, 1>(bufA, bufB, sW[2], sSC + 64, sSH + 64, sBI + 64, cp, j, seq_base);
    __syncthreads();
    conv_layer_cp<32, 7, 512, 7, 1>(bufB, bufA, sW[3], sSC + 96, sSH + 96, sBI + 96, cp, j, seq_base);
    __syncthreads();

    // ---- per-position MLP: 32 -> 16 (ReLU) -> 1 ; one thread per position ----
    float yc[32];
#pragma unroll
    for (int c = 0; c < 32; ++c) yc[c] = bufA[c * WPAD + HALO + tid];

    float o = sFB2[0];
#pragma unroll
    for (int i = 0; i < 16; ++i) {
        float h = sFB1[i];
#pragma unroll
        for (int c = 0; c < 32; ++c) h = fmaf(sFW1[i * 32 + c], yc[c], h);
        o = fmaf(fmaxf(h, 0.f), sFW2[i], o);
    }
    out[b * SEQ + ts + tid] = o;
}

extern "C" void kernel_launch(void* const* d_in, const int* in_sizes, int n_in,
                              void* d_out, int out_size)
{
    Ptrs P;
    P.x = (const float*)d_in[0];
    for (int l = 0; l < 4; ++l) {
        P.w[l]  = (const float*)d_in[1 + 6 * l];
        P.b[l]  = (const float*)d_in[2 + 6 * l];
        P.g[l]  = (const float*)d_in[3 + 6 * l];
        P.bb[l] = (const float*)d_in[4 + 6 * l];
        P.rm[l] = (const float*)d_in[5 + 6 * l];
        P.rv[l] = (const float*)d_in[6 + 6 * l];
    }
    P.fw1 = (const float*)d_in[25];
    P.fb1 = (const float*)d_in[26];
    P.fw2 = (const float*)d_in[27];
    P.fb2 = (const float*)d_in[28];

    cudaFuncSetAttribute(dna_fused_kernel,
                         cudaFuncAttributeMaxDynamicSharedMemorySize, SMEM_BYTES);

    dim3 grid(SEQ / TSIZE, BATCH);
    dna_fused_kernel<<<grid, NTHREADS, SMEM_BYTES>>>(P, (float*)d_out);
}